// round 2
// baseline (speedup 1.0000x reference)
#include <cuda_runtime.h>
#include <cstdint>

// Problem constants
#define BB 4096
#define NN 8192
#define THREADS 512
#define VECW 4
#define ITERS (NN / (THREADS * VECW))   // 4 float4 loads per thread

#define TAU_SYN_INV 0.5f
#define TAU_MEM_INV 0.5f
#define V_TH 1.0f
#define V_RESET 0.0f
#define INHIB (-5.0f)

__device__ __forceinline__ void argmax_combine(float& bv, int& bi, float ov, int oi) {
    // first-max tie-break: strictly greater wins; equal -> smaller index wins
    if (ov > bv || (ov == bv && oi < bi)) { bv = ov; bi = oi; }
}

__global__ void __launch_bounds__(THREADS, 2)
lif_lateral_inhibition_kernel(const float* __restrict__ x,
                              const float* __restrict__ v,
                              const float* __restrict__ icur,
                              float* __restrict__ z_out,
                              float* __restrict__ v_out,
                              float* __restrict__ i_out) {
    const int row = blockIdx.x;
    const int t   = threadIdx.x;
    const size_t base = (size_t)row * NN;

    const float4* __restrict__ x4 = (const float4*)(x    + base);
    const float4* __restrict__ v4 = (const float4*)(v    + base);
    const float4* __restrict__ c4 = (const float4*)(icur + base);
    float4* __restrict__ z4  = (float4*)(z_out + base);
    float4* __restrict__ io4 = (float4*)(i_out + base);
    float4* __restrict__ vo4 = (float4*)(v_out + base);

    const float NEG_INF = __int_as_float(0xff800000u);

    // keep v_new resident in registers so phase 2 needs no re-read
    float vn[ITERS][VECW];

    float best = NEG_INF;
    int   bidx = 0x7fffffff;

    #pragma unroll
    for (int k = 0; k < ITERS; k++) {
        const int q = k * THREADS + t;        // float4 index within row
        float4 xv = x4[q];
        float4 vv = v4[q];
        float4 cv = c4[q];

        float4 in4, zz4;
        const float* xp = &xv.x;
        const float* vp = &vv.x;
        const float* cp = &cv.x;
        float* ip = &in4.x;
        float* zp = &zz4.x;

        #pragma unroll
        for (int c = 0; c < VECW; c++) {
            float inew = cp[c] + TAU_SYN_INV * (xp[c] - cp[c]);
            float vnew = vp[c] + TAU_MEM_INV * (inew - vp[c]);
            float zc   = (vnew >= V_TH) ? 1.0f : 0.0f;
            ip[c] = inew;
            zp[c] = zc;
            vn[k][c] = vnew;
            if (zc > 0.0f) {
                argmax_combine(best, bidx, vnew, q * VECW + c);
            }
        }
        io4[q] = in4;
        z4[q]  = zz4;
    }

    // ---- block argmax reduction (first-max semantics) ----
    #pragma unroll
    for (int off = 16; off > 0; off >>= 1) {
        float ov = __shfl_xor_sync(0xffffffffu, best, off);
        int   oi = __shfl_xor_sync(0xffffffffu, bidx, off);
        argmax_combine(best, bidx, ov, oi);
    }

    __shared__ float sval[THREADS / 32];
    __shared__ int   sidx[THREADS / 32];
    __shared__ float s_best;
    __shared__ int   s_widx;

    const int lane = t & 31;
    const int warp = t >> 5;
    if (lane == 0) { sval[warp] = best; sidx[warp] = bidx; }
    __syncthreads();

    if (warp == 0) {
        float bv = (lane < THREADS / 32) ? sval[lane] : NEG_INF;
        int   bi = (lane < THREADS / 32) ? sidx[lane] : 0x7fffffff;
        #pragma unroll
        for (int off = 16; off > 0; off >>= 1) {
            float ov = __shfl_xor_sync(0xffffffffu, bv, off);
            int   oi = __shfl_xor_sync(0xffffffffu, bi, off);
            argmax_combine(bv, bi, ov, oi);
        }
        if (lane == 0) { s_best = bv; s_widx = bi; }
    }
    __syncthreads();

    const bool  any_spike = (s_best >= V_TH);   // scores only include spiked -> max>=V_TH iff any spike
    const int   widx      = s_widx;

    // ---- phase 2: v_out from registers ----
    #pragma unroll
    for (int k = 0; k < ITERS; k++) {
        const int q = k * THREADS + t;
        float4 out4;
        float* op = &out4.x;
        #pragma unroll
        for (int c = 0; c < VECW; c++) {
            float vnew   = vn[k][c];
            float vafter = (vnew >= V_TH) ? V_RESET : vnew;
            int   gidx   = q * VECW + c;
            float val;
            if (any_spike) {
                val = (gidx == widx) ? vafter : INHIB;
            } else {
                val = vafter;
            }
            op[c] = val;
        }
        vo4[q] = out4;
    }
}

extern "C" void kernel_launch(void* const* d_in, const int* in_sizes, int n_in,
                              void* d_out, int out_size) {
    const float* x = (const float*)d_in[0];
    const float* v = (const float*)d_in[1];
    const float* i = (const float*)d_in[2];

    float* out   = (float*)d_out;
    float* z_out = out;                           // [B, N]
    float* v_out = out + (size_t)BB * NN;         // [B, N]
    float* i_out = out + 2 * (size_t)BB * NN;     // [B, N]

    lif_lateral_inhibition_kernel<<<BB, THREADS>>>(x, v, i, z_out, v_out, i_out);
}